// round 1
// baseline (speedup 1.0000x reference)
#include <cuda_runtime.h>
#include <math.h>

// Problem constants (fixed shapes from reference)
#define BB 32
#define CC 16
#define LL 4096
#define SS 64
#define KK 64
#define WW 4033          // LL - SS + 1

#define W_TILE 128
#define T 16                     // windows per thread
#define WGROUPS (W_TILE / T)     // 8
#define NTHREADS (KK * WGROUPS)  // 512
#define XS_STRIDE 192            // W_TILE + SS - 1 + 1 (refill headroom)

// Scratch (no dynamic allocation allowed)
__device__ float g_shn_t[CC * SS * KK];          // normalized shapelets, [c][s][k]
__device__ float g_invn[(size_t)BB * CC * WW];   // 1/max(||win||,eps), [b][c][w]

// ---------------------------------------------------------------------------
// Kernel 1: normalize shapelets and transpose to [c][s][k]
// grid = C*K rows, 32 threads (one warp) per row
// ---------------------------------------------------------------------------
__global__ void norm_shapelets_kernel(const float* __restrict__ sh) {
    int row  = blockIdx.x;          // c*KK + k
    int c    = row / KK;
    int k    = row - c * KK;
    int lane = threadIdx.x;         // 0..31
    const float* p = sh + (size_t)row * SS;
    float v0 = p[lane];
    float v1 = p[lane + 32];
    float ss = v0 * v0 + v1 * v1;
    #pragma unroll
    for (int o = 16; o > 0; o >>= 1) ss += __shfl_xor_sync(0xffffffffu, ss, o);
    float inv = 1.0f / fmaxf(sqrtf(ss), 1e-8f);
    g_shn_t[(c * SS + lane) * KK + k]        = v0 * inv;
    g_shn_t[(c * SS + lane + 32) * KK + k]   = v1 * inv;
}

// ---------------------------------------------------------------------------
// Kernel 2: inverse window norms. One block per (b,c) row.
// ---------------------------------------------------------------------------
__global__ void win_invnorm_kernel(const float* __restrict__ x) {
    __shared__ float xs[LL];
    int row = blockIdx.x;           // b*CC + c
    const float* xr = x + (size_t)row * LL;
    for (int i = threadIdx.x; i < LL; i += blockDim.x) xs[i] = xr[i];
    __syncthreads();
    for (int w = threadIdx.x; w < WW; w += blockDim.x) {
        float ss = 0.0f;
        #pragma unroll
        for (int s = 0; s < SS; ++s) {
            float v = xs[w + s];
            ss = fmaf(v, v, ss);
        }
        g_invn[(size_t)row * WW + w] = 1.0f / fmaxf(sqrtf(ss), 1e-8f);
    }
}

// ---------------------------------------------------------------------------
// Kernel 3: zero output (harness poisons d_out; relu floor is 0)
// ---------------------------------------------------------------------------
__global__ void zero_out_kernel(float* __restrict__ out) {
    out[blockIdx.x * 256 + threadIdx.x] = 0.0f;
}

// ---------------------------------------------------------------------------
// Kernel 4: main conv + scale + relu-max.
// grid = (num W tiles, B). Block: 512 threads = 64 k * 8 w-groups of T=16.
// Register shift-ring conv: per s-step, 16 FFMA + 1 LDS (shv) + 1 LDS (refill).
// ---------------------------------------------------------------------------
__global__ void __launch_bounds__(NTHREADS)
max_cossim_kernel(const float* __restrict__ x, float* __restrict__ out) {
    __shared__ float xs[CC * XS_STRIDE];   // 3072 floats, x tile (zero-padded)
    __shared__ float shn[SS * KK];         // 4096 floats, one c-slice, [s][k]
    __shared__ float invs[CC * W_TILE];    // 2048 floats, inv norms (reused for reduce)

    const int b  = blockIdx.y;
    const int w0 = blockIdx.x * W_TILE;
    const int t  = threadIdx.x;
    const int k  = t & (KK - 1);
    const int wg = t >> 6;
    const int lb = wg * T;

    // Load x tile (all 16 channels, W_TILE + 63 + pad samples), zero-pad OOB.
    const float* xb = x + (size_t)b * CC * LL;
    for (int idx = t; idx < CC * XS_STRIDE; idx += NTHREADS) {
        int c = idx / XS_STRIDE;
        int j = idx - c * XS_STRIDE;
        int gw = w0 + j;
        xs[idx] = (gw < LL) ? xb[(size_t)c * LL + gw] : 0.0f;
    }
    // Load inverse-norm tile.
    for (int idx = t; idx < CC * W_TILE; idx += NTHREADS) {
        int c = idx / W_TILE;
        int j = idx - c * W_TILE;
        int gw = w0 + j;
        invs[idx] = (gw < WW) ? g_invn[((size_t)b * CC + c) * WW + gw] : 0.0f;
    }
    __syncthreads();

    float acc[T];
    #pragma unroll
    for (int i = 0; i < T; ++i) acc[i] = 0.0f;

    for (int c = 0; c < CC; ++c) {
        // Stage normalized shapelet slice [s][k] for this channel.
        __syncthreads();
        {
            const float4* src = (const float4*)(g_shn_t + (size_t)c * SS * KK);
            float4* dst = (float4*)shn;
            for (int idx = t; idx < (SS * KK) / 4; idx += NTHREADS) dst[idx] = src[idx];
        }
        __syncthreads();

        const float* xr = xs + c * XS_STRIDE + lb;

        float ring[16];
        #pragma unroll
        for (int j = 0; j < 16; ++j) ring[j] = xr[j];

        float dot[T];
        #pragma unroll
        for (int i = 0; i < T; ++i) dot[i] = 0.0f;

        // s = so*16 + sp; ring invariant: ring[(s+j)&15] == x[lb+s+j]
        for (int so = 0; so < 4; ++so) {
            int sbase = so * 16;
            #pragma unroll
            for (int sp = 0; sp < 16; ++sp) {
                float shv = shn[(sbase + sp) * KK + k];
                #pragma unroll
                for (int i = 0; i < T; ++i)
                    dot[i] = fmaf(ring[(sp + i) & 15], shv, dot[i]);
                ring[sp] = xr[sbase + sp + 16];   // (s & 15) == sp since sbase%16==0
            }
        }

        const float* ivp = invs + c * W_TILE + lb;
        #pragma unroll
        for (int i = 0; i < T; ++i) acc[i] = fmaf(ivp[i], dot[i], acc[i]);
    }

    // Epilogue: sim = acc/C, relu + max over this thread's valid windows.
    float m = 0.0f;
    #pragma unroll
    for (int i = 0; i < T; ++i) {
        int w = w0 + lb + i;
        float sim = acc[i] * (1.0f / (float)CC);
        if (w < WW) m = fmaxf(m, sim);
    }

    // Block reduce across the 8 w-groups per k, then one atomic per (b,k,tile).
    __syncthreads();                 // invs reads done; safe to reuse as scratch
    float* red = invs;
    red[wg * KK + k] = m;
    __syncthreads();
    if (wg == 0) {
        #pragma unroll
        for (int g = 1; g < WGROUPS; ++g) m = fmaxf(m, red[g * KK + k]);
        // m >= 0, so float bit pattern is monotone: int atomicMax is exact.
        atomicMax((int*)&out[b * KK + k], __float_as_int(m));
    }
}

// ---------------------------------------------------------------------------
// Launch
// ---------------------------------------------------------------------------
extern "C" void kernel_launch(void* const* d_in, const int* in_sizes, int n_in,
                              void* d_out, int out_size) {
    const float* x  = (const float*)d_in[0];   // (32,16,4096) f32
    const float* sh = (const float*)d_in[1];   // (16,64,64)  f32
    float* out = (float*)d_out;                // (32,1,64)   f32

    norm_shapelets_kernel<<<CC * KK, 32>>>(sh);
    win_invnorm_kernel<<<BB * CC, 256>>>(x);
    zero_out_kernel<<<(BB * KK) / 256, 256>>>(out);

    dim3 grid((WW + W_TILE - 1) / W_TILE, BB);   // (32, 32)
    max_cossim_kernel<<<grid, NTHREADS>>>(x, out);
}

// round 3
// speedup vs baseline: 1.1901x; 1.1901x over previous
#include <cuda_runtime.h>
#include <math.h>

// Problem constants (fixed shapes from reference)
#define BB 32
#define CC 16
#define LL 4096
#define SS 64
#define KK 64
#define WW 4033          // LL - SS + 1

#define W_TILE 128
#define T 8                      // windows per thread
#define K4 4                     // shapelets per thread (2x f32x2)
#define KQ (KK / K4)             // 16 kquads
#define WGROUPS (W_TILE / T)     // 16
#define NTHREADS (KQ * WGROUPS)  // 256
#define XS_STRIDE 192            // W_TILE + SS (refill headroom)

// Dynamic shared memory layout (floats):
//   xs   : CC * XS_STRIDE           = 3072   (12 KB)
//   shn  : 2 * SS * KK              = 8192   (32 KB, double-buffered)
//   invs : CC * W_TILE              = 2048   ( 8 KB)
#define SMEM_XS_OFF   0
#define SMEM_SHN_OFF  (CC * XS_STRIDE)
#define SMEM_INV_OFF  (SMEM_SHN_OFF + 2 * SS * KK)
#define SMEM_FLOATS   (SMEM_INV_OFF + CC * W_TILE)
#define SMEM_BYTES    (SMEM_FLOATS * 4)

typedef unsigned long long ull;

// Scratch (no dynamic allocation allowed)
__device__ float g_shn_t[CC * SS * KK];          // normalized shapelets, [c][s][k]
__device__ float g_invn[(size_t)BB * CC * WW];   // 1/max(||win||,eps), [b][c][w]

// ---------------------------------------------------------------------------
// Packed f32x2 helpers (Blackwell)
// ---------------------------------------------------------------------------
__device__ __forceinline__ ull fma2(ull a, ull b, ull c) {
    ull d;
    asm("fma.rn.f32x2 %0, %1, %2, %3;" : "=l"(d) : "l"(a), "l"(b), "l"(c));
    return d;
}
__device__ __forceinline__ ull dup2(float v) {
    ull d;
    unsigned int u = __float_as_uint(v);
    asm("mov.b64 %0, {%1, %1};" : "=l"(d) : "r"(u));
    return d;
}
__device__ __forceinline__ float2 unpack2(ull v) {
    unsigned int lo, hi;
    asm("mov.b64 {%0, %1}, %2;" : "=r"(lo), "=r"(hi) : "l"(v));
    float2 f;
    f.x = __uint_as_float(lo);
    f.y = __uint_as_float(hi);
    return f;
}

// ---------------------------------------------------------------------------
// Kernel 1: normalize shapelets and transpose to [c][s][k]
// ---------------------------------------------------------------------------
__global__ void norm_shapelets_kernel(const float* __restrict__ sh) {
    int row  = blockIdx.x;          // c*KK + k
    int c    = row / KK;
    int k    = row - c * KK;
    int lane = threadIdx.x;
    const float* p = sh + (size_t)row * SS;
    float v0 = p[lane];
    float v1 = p[lane + 32];
    float ss = v0 * v0 + v1 * v1;
    #pragma unroll
    for (int o = 16; o > 0; o >>= 1) ss += __shfl_xor_sync(0xffffffffu, ss, o);
    float inv = 1.0f / fmaxf(sqrtf(ss), 1e-8f);
    g_shn_t[(c * SS + lane) * KK + k]        = v0 * inv;
    g_shn_t[(c * SS + lane + 32) * KK + k]   = v1 * inv;
}

// ---------------------------------------------------------------------------
// Kernel 2: inverse window norms via chunked sliding sum-of-squares.
// One block per (b,c) row; each thread owns 16 consecutive windows.
// ---------------------------------------------------------------------------
__device__ __forceinline__ float inv_norm(float ss) {
    return (ss > 1e-16f) ? rsqrtf(ss) : 1e8f;
}

__global__ void win_invnorm_kernel(const float* __restrict__ x) {
    __shared__ float xs[LL];
    int row = blockIdx.x;           // b*CC + c
    const float* xr = x + (size_t)row * LL;
    for (int i = threadIdx.x; i < LL; i += blockDim.x) xs[i] = xr[i];
    __syncthreads();
    int wbase = threadIdx.x * 16;   // 256 threads * 16 = 4096 >= WW
    if (wbase < WW) {
        float* dst = g_invn + (size_t)row * WW;
        float ss = 0.0f;
        #pragma unroll
        for (int s = 0; s < SS; ++s) {
            float v = xs[wbase + s];
            ss = fmaf(v, v, ss);
        }
        dst[wbase] = inv_norm(ss);
        #pragma unroll
        for (int j = 1; j < 16; ++j) {
            int w = wbase + j;
            if (w < WW) {
                float add = xs[w + SS - 1];
                float sub = xs[w - 1];
                ss = fmaf(add, add, ss);
                ss = fmaf(-sub, sub, ss);
                dst[w] = inv_norm(ss);
            }
        }
    }
}

// ---------------------------------------------------------------------------
// Kernel 3: zero output
// ---------------------------------------------------------------------------
__global__ void zero_out_kernel(float* __restrict__ out) {
    out[blockIdx.x * 256 + threadIdx.x] = 0.0f;
}

// ---------------------------------------------------------------------------
// Kernel 4: main conv + scale + relu-max, packed f32x2.
// grid = (W tiles, B). Block: 256 threads = 16 kquads * 16 w-groups of T=8.
// Register shift-ring holds pre-duplicated {x,x} pairs; per s-step:
// 16 FFMA2 (= 32 MACs) + 1 LDS.128 + 1 LDS + 1 mov.b64.
// ---------------------------------------------------------------------------
__global__ void __launch_bounds__(NTHREADS)
max_cossim_kernel(const float* __restrict__ x, float* __restrict__ out) {
    extern __shared__ float smem[];
    float* xs   = smem + SMEM_XS_OFF;    // CC * XS_STRIDE, zero-padded x tile
    float* shnb = smem + SMEM_SHN_OFF;   // 2 * SS*KK, double-buffered c-slice [s][k]
    float* invs = smem + SMEM_INV_OFF;   // CC * W_TILE (reused for reduce)

    const int b  = blockIdx.y;
    const int w0 = blockIdx.x * W_TILE;
    const int t  = threadIdx.x;
    const int kq = t & (KQ - 1);          // 0..15  -> k = 4*kq
    const int wg = t >> 4;                // 0..15
    const int lb = wg * T;

    // Load x tile (all channels), zero-pad OOB.
    const float* xb = x + (size_t)b * CC * LL;
    for (int idx = t; idx < CC * XS_STRIDE; idx += NTHREADS) {
        int c = idx / XS_STRIDE;
        int j = idx - c * XS_STRIDE;
        int gw = w0 + j;
        xs[idx] = (gw < LL) ? xb[(size_t)c * LL + gw] : 0.0f;
    }
    // Load inverse-norm tile (zero for OOB windows -> dead contribution).
    for (int idx = t; idx < CC * W_TILE; idx += NTHREADS) {
        int c = idx / W_TILE;
        int j = idx - c * W_TILE;
        int gw = w0 + j;
        invs[idx] = (gw < WW) ? g_invn[((size_t)b * CC + c) * WW + gw] : 0.0f;
    }
    // Stage c=0 shapelet slice.
    {
        const float4* src = (const float4*)(g_shn_t);
        float4* dst = (float4*)shnb;
        #pragma unroll
        for (int r = 0; r < (SS * KK / 4) / NTHREADS; ++r)
            dst[t + r * NTHREADS] = src[t + r * NTHREADS];
    }
    __syncthreads();

    ull aA[T], aB[T];
    #pragma unroll
    for (int i = 0; i < T; ++i) { aA[i] = 0ull; aB[i] = 0ull; }

    for (int c = 0; c < CC; ++c) {
        // Prefetch next c-slice into the other buffer (overlaps with compute).
        if (c + 1 < CC) {
            const float4* src = (const float4*)(g_shn_t + (size_t)(c + 1) * SS * KK);
            float4* dst = (float4*)(shnb + ((c + 1) & 1) * (SS * KK));
            #pragma unroll
            for (int r = 0; r < (SS * KK / 4) / NTHREADS; ++r)
                dst[t + r * NTHREADS] = src[t + r * NTHREADS];
        }

        const float* xr = xs + c * XS_STRIDE + lb;
        const float* B  = shnb + (c & 1) * (SS * KK) + 4 * kq;

        // Init ring with pre-duplicated pairs.
        ull rd[T];
        #pragma unroll
        for (int j = 0; j < T; ++j) rd[j] = dup2(xr[j]);

        ull dA[T], dB[T];
        #pragma unroll
        for (int i = 0; i < T; ++i) { dA[i] = 0ull; dB[i] = 0ull; }

        // s = so*8 + sp; ring invariant: rd[(s+j)&7] == dup(x[lb+s+j])
        for (int so = 0; so < SS / T; ++so) {
            const float* xrs = xr + so * T;
            const float* Bs  = B + (so * T) * KK;
            #pragma unroll
            for (int sp = 0; sp < T; ++sp) {
                ulonglong2 sv = *(const ulonglong2*)(Bs + sp * KK);
                #pragma unroll
                for (int i = 0; i < T; ++i) {
                    ull r = rd[(sp + i) & (T - 1)];
                    dA[i] = fma2(r, sv.x, dA[i]);
                    dB[i] = fma2(r, sv.y, dB[i]);
                }
                rd[sp] = dup2(xrs[sp + T]);
            }
        }

        // acc += invn * dot  (invn broadcast-duplicated per window)
        const float* ivp = invs + c * W_TILE + lb;
        #pragma unroll
        for (int i = 0; i < T; ++i) {
            ull dv = dup2(ivp[i]);
            aA[i] = fma2(dv, dA[i], aA[i]);
            aB[i] = fma2(dv, dB[i], aB[i]);
        }
        __syncthreads();   // staging of next slice complete; invs reads done this c
    }

    // Epilogue: relu-max over this thread's valid windows (per 4 k's).
    float m0 = 0.0f, m1 = 0.0f, m2 = 0.0f, m3 = 0.0f;
    #pragma unroll
    for (int i = 0; i < T; ++i) {
        if (w0 + lb + i < WW) {
            float2 a = unpack2(aA[i]);
            float2 c2 = unpack2(aB[i]);
            m0 = fmaxf(m0, a.x);
            m1 = fmaxf(m1, a.y);
            m2 = fmaxf(m2, c2.x);
            m3 = fmaxf(m3, c2.y);
        }
    }

    // Block reduce across 16 w-groups per k (reuse invs as scratch).
    float* red = invs;
    red[wg * KK + 4 * kq + 0] = m0;
    red[wg * KK + 4 * kq + 1] = m1;
    red[wg * KK + 4 * kq + 2] = m2;
    red[wg * KK + 4 * kq + 3] = m3;
    __syncthreads();
    if (t < KK) {
        float m = red[t];
        #pragma unroll
        for (int g = 1; g < WGROUPS; ++g) m = fmaxf(m, red[g * KK + t]);
        m *= (1.0f / (float)CC);
        // m >= 0: float bits monotone, int atomicMax exact.
        atomicMax((int*)&out[b * KK + t], __float_as_int(m));
    }
}

// ---------------------------------------------------------------------------
// Launch
// ---------------------------------------------------------------------------
extern "C" void kernel_launch(void* const* d_in, const int* in_sizes, int n_in,
                              void* d_out, int out_size) {
    const float* x  = (const float*)d_in[0];   // (32,16,4096) f32
    const float* sh = (const float*)d_in[1];   // (16,64,64)  f32
    float* out = (float*)d_out;                // (32,1,64)   f32

    // Raise dynamic smem limit (idempotent; host-side attribute, not an alloc).
    cudaFuncSetAttribute(max_cossim_kernel,
                         cudaFuncAttributeMaxDynamicSharedMemorySize, SMEM_BYTES);

    norm_shapelets_kernel<<<CC * KK, 32>>>(sh);
    win_invnorm_kernel<<<BB * CC, 256>>>(x);
    zero_out_kernel<<<(BB * KK) / 256, 256>>>(out);

    dim3 grid((WW + W_TILE - 1) / W_TILE, BB);   // (32, 32)
    max_cossim_kernel<<<grid, NTHREADS, SMEM_BYTES>>>(x, out);
}

// round 6
// speedup vs baseline: 1.7680x; 1.4857x over previous
#include <cuda_runtime.h>
#include <cuda_bf16.h>
#include <math.h>

// Problem constants
#define BB 32
#define CC 16
#define LL 4096
#define SS 64
#define KK 64
#define WW 4033            // LL - SS + 1

#define W_TILE 128
#define NT 256             // 8 warps
#define XS_STRIDE 192      // W_TILE + SS headroom (zero-padded)

// ---------------- dynamic smem layout (bytes) ----------------
// A: 128 w-rows x 64 s bf16, hi 16KB + lo 16KB (SW128-swizzled rows of 128B)
// B: 64 k-rows x 64 s bf16, hi 8KB + lo 8KB  (same layout)
#define OFF_A    0
#define OFF_B    32768
#define OFF_XS   49152                          // CC*XS_STRIDE floats = 12KB
#define OFF_INV  (OFF_XS + CC * XS_STRIDE * 4)  // CC*W_TILE floats = 8KB
#define SMEM_BYTES (OFF_INV + CC * W_TILE * 4)  // 69632

typedef unsigned int u32;

// Global scratch
__device__ float g_invn[(size_t)BB * CC * WW];   // 1/max(||win||,eps)
__device__ unsigned char g_shb[CC * 16384];      // per-c swizzled B image: hi @0, lo @8192

// ---------------- helpers ----------------
__device__ __forceinline__ u32 smem_u32(const void* p) {
    u32 a;
    asm("{ .reg .u64 t; cvta.to.shared.u64 t, %1; cvt.u32.u64 %0, t; }" : "=r"(a) : "l"(p));
    return a;
}
__device__ __forceinline__ u32 swz128(u32 off) { return off ^ ((off >> 3) & 0x70); }

__device__ __forceinline__ void ldsm4(u32& r0, u32& r1, u32& r2, u32& r3, u32 addr) {
    asm volatile("ldmatrix.sync.aligned.m8n8.x4.shared.b16 {%0,%1,%2,%3}, [%4];"
                 : "=r"(r0), "=r"(r1), "=r"(r2), "=r"(r3) : "r"(addr));
}
__device__ __forceinline__ void mma_bf16(float* d, u32 a0, u32 a1, u32 a2, u32 a3,
                                         u32 b0, u32 b1) {
    asm volatile(
        "mma.sync.aligned.m16n8k16.row.col.f32.bf16.bf16.f32 "
        "{%0,%1,%2,%3}, {%4,%5,%6,%7}, {%8,%9}, {%0,%1,%2,%3};"
        : "+f"(d[0]), "+f"(d[1]), "+f"(d[2]), "+f"(d[3])
        : "r"(a0), "r"(a1), "r"(a2), "r"(a3), "r"(b0), "r"(b1));
}

// ---------------------------------------------------------------------------
// Prep 1: normalize shapelets, bf16 split, write swizzled B image per c.
// ---------------------------------------------------------------------------
__global__ void norm_shapelets_kernel(const float* __restrict__ sh) {
    int row  = blockIdx.x;          // c*KK + k
    int c    = row / KK;
    int k    = row - c * KK;
    int lane = threadIdx.x;
    const float* p = sh + (size_t)row * SS;
    float v0 = p[lane];
    float v1 = p[lane + 32];
    float ss = v0 * v0 + v1 * v1;
    #pragma unroll
    for (int o = 16; o > 0; o >>= 1) ss += __shfl_xor_sync(0xffffffffu, ss, o);
    float inv = 1.0f / fmaxf(sqrtf(ss), 1e-8f);

    unsigned char* img = g_shb + c * 16384;
    #pragma unroll
    for (int h = 0; h < 2; ++h) {
        int s = lane + 32 * h;
        float vn = (h ? v1 : v0) * inv;
        __nv_bfloat16 hb = __float2bfloat16(vn);
        float hf = __bfloat162float(hb);
        __nv_bfloat16 lb = __float2bfloat16(vn - hf);
        u32 sw = swz128((u32)(k * 128 + s * 2));
        *(unsigned short*)(img + sw)        = __bfloat16_as_ushort(hb);
        *(unsigned short*)(img + 8192 + sw) = __bfloat16_as_ushort(lb);
    }
}

// ---------------------------------------------------------------------------
// Prep 2: inverse window norms, chunked sliding sum-of-squares.
// ---------------------------------------------------------------------------
__device__ __forceinline__ float inv_norm(float ss) {
    return (ss > 1e-16f) ? rsqrtf(ss) : 1e8f;
}
__global__ void win_invnorm_kernel(const float* __restrict__ x) {
    __shared__ float xs[LL];
    int row = blockIdx.x;           // b*CC + c
    const float* xr = x + (size_t)row * LL;
    for (int i = threadIdx.x; i < LL; i += blockDim.x) xs[i] = xr[i];
    __syncthreads();
    int wbase = threadIdx.x * 16;
    if (wbase < WW) {
        float* dst = g_invn + (size_t)row * WW;
        float ss = 0.0f;
        #pragma unroll
        for (int s = 0; s < SS; ++s) { float v = xs[wbase + s]; ss = fmaf(v, v, ss); }
        dst[wbase] = inv_norm(ss);
        #pragma unroll
        for (int j = 1; j < 16; ++j) {
            int w = wbase + j;
            if (w < WW) {
                float a = xs[w + SS - 1], s0 = xs[w - 1];
                ss = fmaf(a, a, ss);
                ss = fmaf(-s0, s0, ss);
                dst[w] = inv_norm(ss);
            }
        }
    }
}

__global__ void zero_out_kernel(float* __restrict__ out) {
    out[blockIdx.x * 256 + threadIdx.x] = 0.0f;
}

// ---------------------------------------------------------------------------
// Main: per (b, w-tile) im2col GEMM via mma.sync (HMMA, register accumulators).
// 8 warps; warp wid computes m-rows [wid*16, wid*16+16) x all 64 k.
// Accumulates 3 split-bf16 terms x 16 channels into 32 fp32 regs/lane.
// ---------------------------------------------------------------------------
__global__ void __launch_bounds__(NT)
max_cossim_kernel(const float* __restrict__ x, float* __restrict__ out) {
    extern __shared__ unsigned char smem[];
    const u32 sbase = smem_u32(smem);
    const int b  = blockIdx.y;
    const int w0 = blockIdx.x * W_TILE;
    const int t  = threadIdx.x;
    const int wid = t >> 5, lane = t & 31;

    float* xs   = (float*)(smem + OFF_XS);
    float* invs = (float*)(smem + OFF_INV);

    // Load x tile (zero-pad OOB) and inv-norm tile (zero OOB windows)
    const float* xb = x + (size_t)b * CC * LL;
    for (int idx = t; idx < CC * XS_STRIDE; idx += NT) {
        int c = idx / XS_STRIDE, j = idx - c * XS_STRIDE;
        int gw = w0 + j;
        xs[idx] = (gw < LL) ? xb[(size_t)c * LL + gw] : 0.0f;
    }
    for (int idx = t; idx < CC * W_TILE; idx += NT) {
        int c = idx / W_TILE, j = idx - c * W_TILE;
        int gw = w0 + j;
        invs[idx] = (gw < WW) ? g_invn[((size_t)b * CC + c) * WW + gw] : 0.0f;
    }

    // ldmatrix lane-address components (constant across c and j)
    const int rx    = lane & 7;                    // swizzle xor (row&7) for A and B
    const int arow  = wid * 16 + ((lane >> 3) & 1) * 8 + (lane & 7);
    const int ahalf = (lane >> 4) & 1;             // chunk half select for A
    const int bn8   = (lane >> 4) & 1;             // ntile-within-pair for B
    const int bhalf = (lane >> 3) & 1;             // chunk half select for B
    const u32 Ah = sbase + OFF_A + (u32)arow * 128;
    const u32 Al = Ah + 16384;
    const u32 Bh = sbase + OFF_B;
    const u32 Bl = Bh + 8192;

    float acc[32];
    #pragma unroll
    for (int i = 0; i < 32; ++i) acc[i] = 0.0f;

    const int r  = t >> 1;            // A-build: row owned by this thread
    const int s0 = (t & 1) * 32;      // A-build: s half

    for (int c = 0; c < CC; ++c) {
        __syncthreads();   // previous compute done before overwriting A/B

        // ---- build A hi/lo (swizzled) ----
        {
            unsigned char* ahi = smem + OFF_A;
            unsigned char* alo = ahi + 16384;
            const float inv = invs[c * W_TILE + r];
            const float* xrow = xs + c * XS_STRIDE + r;
            #pragma unroll
            for (int s2 = 0; s2 < 16; ++s2) {
                int s = s0 + 2 * s2;
                float v0 = inv * xrow[s];
                float v1 = inv * xrow[s + 1];
                __nv_bfloat16 h0 = __float2bfloat16(v0);
                __nv_bfloat16 h1 = __float2bfloat16(v1);
                __nv_bfloat16 l0 = __float2bfloat16(v0 - __bfloat162float(h0));
                __nv_bfloat16 l1 = __float2bfloat16(v1 - __bfloat162float(h1));
                u32 hw = (u32)__bfloat16_as_ushort(h0) | ((u32)__bfloat16_as_ushort(h1) << 16);
                u32 lw = (u32)__bfloat16_as_ushort(l0) | ((u32)__bfloat16_as_ushort(l1) << 16);
                u32 sw = swz128((u32)(r * 128 + s * 2));
                *(u32*)(ahi + sw) = hw;
                *(u32*)(alo + sw) = lw;
            }
        }
        // ---- stage B hi/lo (prestored swizzled image; linear copy) ----
        {
            const uint4* src = (const uint4*)(g_shb + c * 16384);
            uint4* dst = (uint4*)(smem + OFF_B);
            #pragma unroll
            for (int i = 0; i < (16384 / 16) / NT; ++i)
                dst[t + i * NT] = src[t + i * NT];
        }
        __syncthreads();

        // ---- compute: 4 k-steps x (A hi/lo, 4 B ntile-pairs, 6 MMA each) ----
        #pragma unroll
        for (int j = 0; j < 4; ++j) {
            u32 ach = (u32)(((2 * j + ahalf) ^ rx) * 16);
            u32 ah0, ah1, ah2, ah3, al0, al1, al2, al3;
            ldsm4(ah0, ah1, ah2, ah3, Ah + ach);
            ldsm4(al0, al1, al2, al3, Al + ach);
            u32 bch = (u32)(((2 * j + bhalf) ^ rx) * 16);
            #pragma unroll
            for (int p = 0; p < 4; ++p) {
                u32 boff = (u32)((p * 16 + bn8 * 8 + (lane & 7)) * 128) + bch;
                u32 bh0, bh1, bh2, bh3, bl0, bl1, bl2, bl3;
                ldsm4(bh0, bh1, bh2, bh3, Bh + boff);
                ldsm4(bl0, bl1, bl2, bl3, Bl + boff);
                float* d0 = acc + (2 * p) * 4;
                float* d1 = acc + (2 * p + 1) * 4;
                mma_bf16(d0, ah0, ah1, ah2, ah3, bh0, bh1);   // hi*hi
                mma_bf16(d1, ah0, ah1, ah2, ah3, bh2, bh3);
                mma_bf16(d0, ah0, ah1, ah2, ah3, bl0, bl1);   // hi*lo
                mma_bf16(d1, ah0, ah1, ah2, ah3, bl2, bl3);
                mma_bf16(d0, al0, al1, al2, al3, bh0, bh1);   // lo*hi
                mma_bf16(d1, al0, al1, al2, al3, bh2, bh3);
            }
        }
    }
    __syncthreads();   // all LDSM done; A region reusable as reduce scratch

    // ---- epilogue: max over w per k ----
    // Fragment: lane (g=lane>>2, tg=lane&3): acc[nt*4+{0,1}] = rows g, cols nt*8+2tg+{0,1};
    //           acc[nt*4+{2,3}] = rows g+8, same cols.
    float colmax[16];
    #pragma unroll
    for (int nt = 0; nt < 8; ++nt) {
        colmax[2 * nt]     = fmaxf(acc[nt * 4 + 0], acc[nt * 4 + 2]);
        colmax[2 * nt + 1] = fmaxf(acc[nt * 4 + 1], acc[nt * 4 + 3]);
    }
    #pragma unroll
    for (int m = 4; m < 32; m <<= 1) {
        #pragma unroll
        for (int i = 0; i < 16; ++i)
            colmax[i] = fmaxf(colmax[i], __shfl_xor_sync(0xffffffffu, colmax[i], m));
    }
    float* red = (float*)(smem + OFF_A);   // [8 warps][64 cols]
    if (lane < 4) {
        #pragma unroll
        for (int nt = 0; nt < 8; ++nt) {
            red[wid * 64 + nt * 8 + lane * 2 + 0] = colmax[2 * nt];
            red[wid * 64 + nt * 8 + lane * 2 + 1] = colmax[2 * nt + 1];
        }
    }
    __syncthreads();
    if (t < KK) {
        float m = 0.0f;                     // relu floor
        #pragma unroll
        for (int g = 0; g < 8; ++g) m = fmaxf(m, red[g * 64 + t]);
        m *= (1.0f / (float)CC);
        // m >= 0: float bits monotone, int atomicMax exact (out zero-initialized).
        atomicMax((int*)&out[b * KK + t], __float_as_int(m));
    }
}

// ---------------------------------------------------------------------------
// Launch
// ---------------------------------------------------------------------------
extern "C" void kernel_launch(void* const* d_in, const int* in_sizes, int n_in,
                              void* d_out, int out_size) {
    const float* x  = (const float*)d_in[0];   // (32,16,4096) f32
    const float* sh = (const float*)d_in[1];   // (16,64,64)  f32
    float* out = (float*)d_out;                // (32,1,64)   f32

    cudaFuncSetAttribute(max_cossim_kernel,
                         cudaFuncAttributeMaxDynamicSharedMemorySize, SMEM_BYTES);

    norm_shapelets_kernel<<<CC * KK, 32>>>(sh);
    win_invnorm_kernel<<<BB * CC, 256>>>(x);
    zero_out_kernel<<<(BB * KK) / 256, 256>>>(out);

    dim3 grid((WW + W_TILE - 1) / W_TILE, BB);   // (32, 32)
    max_cossim_kernel<<<grid, NT, SMEM_BYTES>>>(x, out);
}

// round 8
// speedup vs baseline: 1.9269x; 1.0899x over previous
#include <cuda_runtime.h>
#include <cuda_bf16.h>
#include <math.h>

// Problem constants
#define BB 32
#define CC 16
#define LL 4096
#define SS 64
#define KK 64
#define WW 4033            // LL - SS + 1

#define W_TILE 256
#define NT 256             // 8 warps, each m32 x n64
#define XS_STRIDE 320      // W_TILE + SS headroom (zero-padded)

// ---------------- dynamic smem layout (bytes) ----------------
// A: 256 w-rows x 64 s bf16, hi 32KB + lo 32KB (SW128-swizzled rows of 128B)
// B: 64 k-rows x 64 s bf16, hi 8KB + lo 8KB  (same layout)
#define OFF_A    0
#define OFF_B    65536
#define OFF_XS   81920                          // CC*XS_STRIDE floats = 20KB
#define SMEM_BYTES (OFF_XS + CC * XS_STRIDE * 4)  // 102400

typedef unsigned int u32;

// Global scratch
__device__ float g_invn[(size_t)BB * CC * WW];   // 1/max(||win||,eps)
__device__ unsigned char g_shb[CC * 16384];      // per-c swizzled B image: hi @0, lo @8192

// ---------------- helpers ----------------
__device__ __forceinline__ u32 smem_u32(const void* p) {
    u32 a;
    asm("{ .reg .u64 t; cvta.to.shared.u64 t, %1; cvt.u32.u64 %0, t; }" : "=r"(a) : "l"(p));
    return a;
}
__device__ __forceinline__ u32 swz128(u32 off) { return off ^ ((off >> 3) & 0x70); }

__device__ __forceinline__ void ldsm4(u32& r0, u32& r1, u32& r2, u32& r3, u32 addr) {
    asm volatile("ldmatrix.sync.aligned.m8n8.x4.shared.b16 {%0,%1,%2,%3}, [%4];"
                 : "=r"(r0), "=r"(r1), "=r"(r2), "=r"(r3) : "r"(addr));
}
__device__ __forceinline__ void mma_bf16(float* d, u32 a0, u32 a1, u32 a2, u32 a3,
                                         u32 b0, u32 b1) {
    asm volatile(
        "mma.sync.aligned.m16n8k16.row.col.f32.bf16.bf16.f32 "
        "{%0,%1,%2,%3}, {%4,%5,%6,%7}, {%8,%9}, {%0,%1,%2,%3};"
        : "+f"(d[0]), "+f"(d[1]), "+f"(d[2]), "+f"(d[3])
        : "r"(a0), "r"(a1), "r"(a2), "r"(a3), "r"(b0), "r"(b1));
}

// ---------------------------------------------------------------------------
// Prep 1: normalize shapelets, bf16 split, write swizzled B image per c.
// ---------------------------------------------------------------------------
__global__ void norm_shapelets_kernel(const float* __restrict__ sh) {
    int row  = blockIdx.x;          // c*KK + k
    int c    = row / KK;
    int k    = row - c * KK;
    int lane = threadIdx.x;
    const float* p = sh + (size_t)row * SS;
    float v0 = p[lane];
    float v1 = p[lane + 32];
    float ss = v0 * v0 + v1 * v1;
    #pragma unroll
    for (int o = 16; o > 0; o >>= 1) ss += __shfl_xor_sync(0xffffffffu, ss, o);
    float inv = 1.0f / fmaxf(sqrtf(ss), 1e-8f);

    unsigned char* img = g_shb + c * 16384;
    #pragma unroll
    for (int h = 0; h < 2; ++h) {
        int s = lane + 32 * h;
        float vn = (h ? v1 : v0) * inv;
        __nv_bfloat16 hb = __float2bfloat16(vn);
        float hf = __bfloat162float(hb);
        __nv_bfloat16 lb = __float2bfloat16(vn - hf);
        u32 sw = swz128((u32)(k * 128 + s * 2));
        *(unsigned short*)(img + sw)        = __bfloat16_as_ushort(hb);
        *(unsigned short*)(img + 8192 + sw) = __bfloat16_as_ushort(lb);
    }
}

// ---------------------------------------------------------------------------
// Prep 2: inverse window norms, chunked sliding sum-of-squares.
// ---------------------------------------------------------------------------
__device__ __forceinline__ float inv_norm(float ss) {
    return (ss > 1e-16f) ? rsqrtf(ss) : 1e8f;
}
__global__ void win_invnorm_kernel(const float* __restrict__ x) {
    __shared__ float xs[LL];
    int row = blockIdx.x;           // b*CC + c
    const float* xr = x + (size_t)row * LL;
    for (int i = threadIdx.x; i < LL; i += blockDim.x) xs[i] = xr[i];
    __syncthreads();
    int wbase = threadIdx.x * 16;
    if (wbase < WW) {
        float* dst = g_invn + (size_t)row * WW;
        float ss = 0.0f;
        #pragma unroll
        for (int s = 0; s < SS; ++s) { float v = xs[wbase + s]; ss = fmaf(v, v, ss); }
        dst[wbase] = inv_norm(ss);
        #pragma unroll
        for (int j = 1; j < 16; ++j) {
            int w = wbase + j;
            if (w < WW) {
                float a = xs[w + SS - 1], s0 = xs[w - 1];
                ss = fmaf(a, a, ss);
                ss = fmaf(-s0, s0, ss);
                dst[w] = inv_norm(ss);
            }
        }
    }
}

__global__ void zero_out_kernel(float* __restrict__ out) {
    out[blockIdx.x * 256 + threadIdx.x] = 0.0f;
}

// ---------------------------------------------------------------------------
// Main: per (b, 256-w tile) im2col GEMM via mma.sync.
// 8 warps; warp wid computes m-rows [wid*32, wid*32+32) x all 64 k.
// 3 split-bf16 terms x 16 channels -> 64 fp32 acc regs/lane.
// B fragments amortized over 2 m-tiles (12 MMAs per B ldsm4-pair).
// ---------------------------------------------------------------------------
__global__ void __launch_bounds__(NT, 2)
max_cossim_kernel(const float* __restrict__ x, float* __restrict__ out) {
    extern __shared__ unsigned char smem[];
    const u32 sbase = smem_u32(smem);
    const int b  = blockIdx.y;
    const int w0 = blockIdx.x * W_TILE;
    const int t  = threadIdx.x;
    const int wid = t >> 5, lane = t & 31;

    float* xs = (float*)(smem + OFF_XS);

    // Load x tile (zero-pad OOB)
    const float* xb = x + (size_t)b * CC * LL;
    for (int idx = t; idx < CC * XS_STRIDE; idx += NT) {
        int c = idx / XS_STRIDE, j = idx - c * XS_STRIDE;
        int gw = w0 + j;
        xs[idx] = (gw < LL) ? xb[(size_t)c * LL + gw] : 0.0f;
    }

    // ldmatrix lane-address components (constant across c and j)
    const int rx    = lane & 7;
    const int asub  = ((lane >> 3) & 1) * 8 + (lane & 7);  // row within m16 tile
    const int ahalf = (lane >> 4) & 1;
    const int bn8   = (lane >> 4) & 1;
    const int bhalf = (lane >> 3) & 1;
    const u32 Ah0 = sbase + OFF_A + (u32)(wid * 32 + asub) * 128;        // mtile 0
    const u32 Ah1 = Ah0 + 16 * 128;                                      // mtile 1
    const u32 Bh  = sbase + OFF_B;

    float acc[64];    // [mtile(2)][ntile(8)][4]
    #pragma unroll
    for (int i = 0; i < 64; ++i) acc[i] = 0.0f;

    const int r = t;                       // A-build: row owned by this thread
    const size_t invbase = ((size_t)b * CC) * WW + (w0 + r);
    float inv_next = (w0 + r < WW) ? g_invn[invbase] : 0.0f;

    for (int c = 0; c < CC; ++c) {
        __syncthreads();   // previous compute done before overwriting A/B

        const float inv = inv_next;
        if (c + 1 < CC)
            inv_next = (w0 + r < WW) ? g_invn[invbase + (size_t)(c + 1) * WW] : 0.0f;

        // ---- build A hi/lo (row r, 64 s values, swizzled) ----
        {
            unsigned char* ahi = smem + OFF_A;
            unsigned char* alo = ahi + 32768;
            const float* xrow = xs + c * XS_STRIDE + r;
            #pragma unroll
            for (int s2 = 0; s2 < 32; ++s2) {
                int s = 2 * s2;
                float v0 = inv * xrow[s];
                float v1 = inv * xrow[s + 1];
                __nv_bfloat162 h = __float22bfloat162_rn(make_float2(v0, v1));
                float2 hf = __bfloat1622float2(h);
                __nv_bfloat162 l = __float22bfloat162_rn(make_float2(v0 - hf.x, v1 - hf.y));
                u32 sw = swz128((u32)(r * 128 + s * 2));
                *(u32*)(ahi + sw) = *(u32*)&h;
                *(u32*)(alo + sw) = *(u32*)&l;
            }
        }
        // ---- stage B hi/lo (prestored swizzled image; linear copy) ----
        {
            const uint4* src = (const uint4*)(g_shb + c * 16384);
            uint4* dst = (uint4*)(smem + OFF_B);
            #pragma unroll
            for (int i = 0; i < (16384 / 16) / NT; ++i)
                dst[t + i * NT] = src[t + i * NT];
        }
        __syncthreads();

        // ---- compute: 4 k-steps; A frags for 2 m-tiles, B shared across them ----
        #pragma unroll
        for (int j = 0; j < 4; ++j) {
            u32 ach = (u32)(((2 * j + ahalf) ^ rx) * 16);
            u32 a0h0, a0h1, a0h2, a0h3, a0l0, a0l1, a0l2, a0l3;
            u32 a1h0, a1h1, a1h2, a1h3, a1l0, a1l1, a1l2, a1l3;
            ldsm4(a0h0, a0h1, a0h2, a0h3, Ah0 + ach);
            ldsm4(a0l0, a0l1, a0l2, a0l3, Ah0 + 32768 + ach);
            ldsm4(a1h0, a1h1, a1h2, a1h3, Ah1 + ach);
            ldsm4(a1l0, a1l1, a1l2, a1l3, Ah1 + 32768 + ach);
            u32 bch = (u32)(((2 * j + bhalf) ^ rx) * 16);
            #pragma unroll
            for (int p = 0; p < 4; ++p) {
                u32 boff = (u32)((p * 16 + bn8 * 8 + (lane & 7)) * 128) + bch;
                u32 bh0, bh1, bh2, bh3, bl0, bl1, bl2, bl3;
                ldsm4(bh0, bh1, bh2, bh3, Bh + boff);
                ldsm4(bl0, bl1, bl2, bl3, Bh + 8192 + boff);
                float* d00 = acc + (0 * 8 + 2 * p) * 4;
                float* d01 = acc + (0 * 8 + 2 * p + 1) * 4;
                float* d10 = acc + (1 * 8 + 2 * p) * 4;
                float* d11 = acc + (1 * 8 + 2 * p + 1) * 4;
                mma_bf16(d00, a0h0, a0h1, a0h2, a0h3, bh0, bh1);   // hi*hi
                mma_bf16(d01, a0h0, a0h1, a0h2, a0h3, bh2, bh3);
                mma_bf16(d10, a1h0, a1h1, a1h2, a1h3, bh0, bh1);
                mma_bf16(d11, a1h0, a1h1, a1h2, a1h3, bh2, bh3);
                mma_bf16(d00, a0h0, a0h1, a0h2, a0h3, bl0, bl1);   // hi*lo
                mma_bf16(d01, a0h0, a0h1, a0h2, a0h3, bl2, bl3);
                mma_bf16(d10, a1h0, a1h1, a1h2, a1h3, bl0, bl1);
                mma_bf16(d11, a1h0, a1h1, a1h2, a1h3, bl2, bl3);
                mma_bf16(d00, a0l0, a0l1, a0l2, a0l3, bh0, bh1);   // lo*hi
                mma_bf16(d01, a0l0, a0l1, a0l2, a0l3, bh2, bh3);
                mma_bf16(d10, a1l0, a1l1, a1l2, a1l3, bh0, bh1);
                mma_bf16(d11, a1l0, a1l1, a1l2, a1l3, bh2, bh3);
            }
        }
    }
    __syncthreads();   // all LDSM done; A region reusable as reduce scratch

    // ---- epilogue: max over w per k ----
    // Fragment: lane (g=lane>>2, tg=lane&3): acc[(m*8+nt)*4+{0,1}] = rows (g, g+8)
    // of mtile m, cols nt*8+2tg+{0,1}; +2,+3 are rows +8. Max over m and row-halves
    // keeps column identity (cols depend only on nt, tg).
    float colmax[16];
    #pragma unroll
    for (int nt = 0; nt < 8; ++nt) {
        float m0 = fmaxf(fmaxf(acc[(0 * 8 + nt) * 4 + 0], acc[(0 * 8 + nt) * 4 + 2]),
                         fmaxf(acc[(1 * 8 + nt) * 4 + 0], acc[(1 * 8 + nt) * 4 + 2]));
        float m1 = fmaxf(fmaxf(acc[(0 * 8 + nt) * 4 + 1], acc[(0 * 8 + nt) * 4 + 3]),
                         fmaxf(acc[(1 * 8 + nt) * 4 + 1], acc[(1 * 8 + nt) * 4 + 3]));
        colmax[2 * nt]     = m0;
        colmax[2 * nt + 1] = m1;
    }
    #pragma unroll
    for (int m = 4; m < 32; m <<= 1) {
        #pragma unroll
        for (int i = 0; i < 16; ++i)
            colmax[i] = fmaxf(colmax[i], __shfl_xor_sync(0xffffffffu, colmax[i], m));
    }
    float* red = (float*)(smem + OFF_A);   // [8 warps][64 cols]
    if (lane < 4) {
        #pragma unroll
        for (int nt = 0; nt < 8; ++nt) {
            red[wid * 64 + nt * 8 + lane * 2 + 0] = colmax[2 * nt];
            red[wid * 64 + nt * 8 + lane * 2 + 1] = colmax[2 * nt + 1];
        }
    }
    __syncthreads();
    if (t < KK) {
        float m = 0.0f;                     // relu floor
        #pragma unroll
        for (int g = 0; g < 8; ++g) m = fmaxf(m, red[g * 64 + t]);
        m *= (1.0f / (float)CC);
        // m >= 0: float bits monotone, int atomicMax exact (out zero-initialized).
        atomicMax((int*)&out[b * KK + t], __float_as_int(m));
    }
}

// ---------------------------------------------------------------------------
// Launch
// ---------------------------------------------------------------------------
extern "C" void kernel_launch(void* const* d_in, const int* in_sizes, int n_in,
                              void* d_out, int out_size) {
    const float* x  = (const float*)d_in[0];   // (32,16,4096) f32
    const float* sh = (const float*)d_in[1];   // (16,64,64)  f32
    float* out = (float*)d_out;                // (32,1,64)   f32

    cudaFuncSetAttribute(max_cossim_kernel,
                         cudaFuncAttributeMaxDynamicSharedMemorySize, SMEM_BYTES);

    norm_shapelets_kernel<<<CC * KK, 32>>>(sh);
    win_invnorm_kernel<<<BB * CC, 256>>>(x);
    zero_out_kernel<<<(BB * KK) / 256, 256>>>(out);

    dim3 grid((WW + W_TILE - 1) / W_TILE, BB);   // (16, 32)
    max_cossim_kernel<<<grid, NT, SMEM_BYTES>>>(x, out);
}